// round 9
// baseline (speedup 1.0000x reference)
#include <cuda_runtime.h>
#include <cuda_bf16.h>

// Level-3 Haar wavelet packet transform, freq (Gray-code) band order.
// x: [R=1024 rows, 65536], out: [R, 8 bands, 8192].
//
// natural band b=(l1,l2,l3): nat[b] = sum_j (-1)^(l1*j0+l2*j1+l3*j2) x[8k+j] * (1/sqrt2)^3
// output band i = nat[perm[i]], perm = [0,1,3,2,6,7,5,4].
//
// One-shot kernel (NOT grid-stride: R7 showed CTA replacement is what keeps
// the DRAM queues full; a persistent loop serializes each warp's loads behind
// its own stores and lost 23%). Each thread: 4 consecutive groups
// (32 floats) via 4x LDG.E.256 with L2::evict_first (read stream is
// never reused -> don't churn L2), 8x STG.128 streaming (.cs) stores.
// Per block, each band's stores form one contiguous 4KB burst.

#define GROUPS_PER_ROW 8192   // 65536 / 8
#define ROW_LEN        65536

__global__ void __launch_bounds__(256, 6)
WaveletPacketTransform_74715251081585_kernel(const float* __restrict__ x,
                                             float* __restrict__ out,
                                             int n_thread_units)  // total_groups / 4
{
    int t = blockIdx.x * blockDim.x + threadIdx.x;
    if (t >= n_thread_units) return;

    const int g0  = t << 2;                 // first group index (flat)
    const int k   = g0 & (GROUPS_PER_ROW - 1);
    const int row = g0 >> 13;               // g0 / 8192

    const float* __restrict__ xin = x + (size_t)g0 * 8;

    const float S = 0.35355339059327373f;   // (1/sqrt2)^3

    float r0[4], r1[4], r2[4], r3[4], r4[4], r5[4], r6[4], r7[4];

#pragma unroll
    for (int q = 0; q < 4; q++) {
        float v0, v1, v2, v3, v4, v5, v6, v7;
        // 256-bit read-only global load (sm_100+), evict-first in L2:
        // this stream is dead after consumption.
        asm("ld.global.nc.L2::evict_first.v8.f32 {%0,%1,%2,%3,%4,%5,%6,%7}, [%8];"
            : "=f"(v0), "=f"(v1), "=f"(v2), "=f"(v3),
              "=f"(v4), "=f"(v5), "=f"(v6), "=f"(v7)
            : "l"(xin + q * 8));

        // level 1: pairwise sum/diff
        float p0 = v0 + v1, m0 = v0 - v1;
        float p1 = v2 + v3, m1 = v2 - v3;
        float p2 = v4 + v5, m2 = v4 - v5;
        float p3 = v6 + v7, m3 = v6 - v7;

        // level 2
        float pp0 = p0 + p1, pm0 = p0 - p1;
        float pp1 = p2 + p3, pm1 = p2 - p3;
        float mp0 = m0 + m1, mm0 = m0 - m1;
        float mp1 = m2 + m3, mm1 = m2 - m3;

        // level 3 + Gray-code output permutation [0,1,3,2,6,7,5,4]
        r0[q] = (pp0 + pp1) * S;   // nat0 aaa
        r1[q] = (pp0 - pp1) * S;   // nat1 aad
        r2[q] = (pm0 - pm1) * S;   // nat3 add
        r3[q] = (pm0 + pm1) * S;   // nat2 ada
        r4[q] = (mm0 + mm1) * S;   // nat6 dda
        r5[q] = (mm0 - mm1) * S;   // nat7 ddd
        r6[q] = (mp0 - mp1) * S;   // nat5 dad
        r7[q] = (mp0 + mp1) * S;   // nat4 daa
    }

    float* __restrict__ ob = out + (size_t)row * ROW_LEN + k;
#define WR(i, a) __stcs(reinterpret_cast<float4*>(ob + (i) * GROUPS_PER_ROW), \
                        make_float4(a[0], a[1], a[2], a[3]))
    WR(0, r0); WR(1, r1); WR(2, r2); WR(3, r3);
    WR(4, r4); WR(5, r5); WR(6, r6); WR(7, r7);
#undef WR
}

extern "C" void kernel_launch(void* const* d_in, const int* in_sizes, int n_in,
                              void* d_out, int out_size)
{
    const float* x = (const float*)d_in[0];
    float* out = (float*)d_out;

    // total elements = 67,108,864; groups = /8; thread units = groups/4
    int n_thread_units = in_sizes[0] / 32;
    int block = 256;
    int grid = (n_thread_units + block - 1) / block;   // 8192 one-shot blocks
    WaveletPacketTransform_74715251081585_kernel<<<grid, block>>>(x, out, n_thread_units);
}

// round 10
// speedup vs baseline: 1.0019x; 1.0019x over previous
#include <cuda_runtime.h>
#include <cuda_bf16.h>

// Level-3 Haar wavelet packet transform, freq (Gray-code) band order.
// x: [R=1024 rows, 65536], out: [R, 8 bands, 8192].
//
// natural band b=(l1,l2,l3): nat[b] = sum_j (-1)^(l1*j0+l2*j1+l3*j2) x[8k+j] * (1/sqrt2)^3
// output band i = nat[perm[i]], perm = [0,1,3,2,6,7,5,4].
//
// One-shot kernel (NOT grid-stride: R7 showed CTA replacement is what keeps
// the DRAM queues full; a persistent loop serializes each warp's loads behind
// its own stores and lost 23%). Each thread: 4 consecutive groups
// (32 floats) via 4x LDG.E.256 with L2::evict_first (read stream is
// never reused -> don't churn L2), 8x STG.128 streaming (.cs) stores.
// Per block, each band's stores form one contiguous 4KB burst.

#define GROUPS_PER_ROW 8192   // 65536 / 8
#define ROW_LEN        65536

__global__ void __launch_bounds__(256, 6)
WaveletPacketTransform_74715251081585_kernel(const float* __restrict__ x,
                                             float* __restrict__ out,
                                             int n_thread_units)  // total_groups / 4
{
    int t = blockIdx.x * blockDim.x + threadIdx.x;
    if (t >= n_thread_units) return;

    const int g0  = t << 2;                 // first group index (flat)
    const int k   = g0 & (GROUPS_PER_ROW - 1);
    const int row = g0 >> 13;               // g0 / 8192

    const float* __restrict__ xin = x + (size_t)g0 * 8;

    const float S = 0.35355339059327373f;   // (1/sqrt2)^3

    float r0[4], r1[4], r2[4], r3[4], r4[4], r5[4], r6[4], r7[4];

#pragma unroll
    for (int q = 0; q < 4; q++) {
        float v0, v1, v2, v3, v4, v5, v6, v7;
        // 256-bit read-only global load (sm_100+), evict-first in L2:
        // this stream is dead after consumption.
        asm("ld.global.nc.L2::evict_first.v8.f32 {%0,%1,%2,%3,%4,%5,%6,%7}, [%8];"
            : "=f"(v0), "=f"(v1), "=f"(v2), "=f"(v3),
              "=f"(v4), "=f"(v5), "=f"(v6), "=f"(v7)
            : "l"(xin + q * 8));

        // level 1: pairwise sum/diff
        float p0 = v0 + v1, m0 = v0 - v1;
        float p1 = v2 + v3, m1 = v2 - v3;
        float p2 = v4 + v5, m2 = v4 - v5;
        float p3 = v6 + v7, m3 = v6 - v7;

        // level 2
        float pp0 = p0 + p1, pm0 = p0 - p1;
        float pp1 = p2 + p3, pm1 = p2 - p3;
        float mp0 = m0 + m1, mm0 = m0 - m1;
        float mp1 = m2 + m3, mm1 = m2 - m3;

        // level 3 + Gray-code output permutation [0,1,3,2,6,7,5,4]
        r0[q] = (pp0 + pp1) * S;   // nat0 aaa
        r1[q] = (pp0 - pp1) * S;   // nat1 aad
        r2[q] = (pm0 - pm1) * S;   // nat3 add
        r3[q] = (pm0 + pm1) * S;   // nat2 ada
        r4[q] = (mm0 + mm1) * S;   // nat6 dda
        r5[q] = (mm0 - mm1) * S;   // nat7 ddd
        r6[q] = (mp0 - mp1) * S;   // nat5 dad
        r7[q] = (mp0 + mp1) * S;   // nat4 daa
    }

    float* __restrict__ ob = out + (size_t)row * ROW_LEN + k;
#define WR(i, a) __stcs(reinterpret_cast<float4*>(ob + (i) * GROUPS_PER_ROW), \
                        make_float4(a[0], a[1], a[2], a[3]))
    WR(0, r0); WR(1, r1); WR(2, r2); WR(3, r3);
    WR(4, r4); WR(5, r5); WR(6, r6); WR(7, r7);
#undef WR
}

extern "C" void kernel_launch(void* const* d_in, const int* in_sizes, int n_in,
                              void* d_out, int out_size)
{
    const float* x = (const float*)d_in[0];
    float* out = (float*)d_out;

    // total elements = 67,108,864; groups = /8; thread units = groups/4
    int n_thread_units = in_sizes[0] / 32;
    int block = 256;
    int grid = (n_thread_units + block - 1) / block;   // 8192 one-shot blocks
    WaveletPacketTransform_74715251081585_kernel<<<grid, block>>>(x, out, n_thread_units);
}

// round 11
// speedup vs baseline: 1.0073x; 1.0054x over previous
#include <cuda_runtime.h>
#include <cuda_bf16.h>

// Level-3 Haar wavelet packet transform, freq (Gray-code) band order.
// x: [R=1024 rows, 65536], out: [R, 8 bands, 8192].
//
// natural band b=(l1,l2,l3): nat[b] = sum_j (-1)^(l1*j0+l2*j1+l3*j2) x[8k+j] * (1/sqrt2)^3
// output band i = nat[perm[i]], perm = [0,1,3,2,6,7,5,4].
//
// One-shot kernel (R7 showed persistent grid-stride loses 23%: CTA
// replacement is the MLP engine — protect it). Each thread: 4 consecutive
// groups (32 floats) via 4x LDG.E.256; 8x STG.128 streaming (.cs) stores.
// Block = 512 threads so each band's per-block write burst is 8KB
// contiguous (fewer, longer write streams for the DRAM scheduler).
// No L2::evict_first — measured slightly worse than plain .nc (R10 vs R6).

#define GROUPS_PER_ROW 8192   // 65536 / 8
#define ROW_LEN        65536

__global__ void __launch_bounds__(512, 3)
WaveletPacketTransform_74715251081585_kernel(const float* __restrict__ x,
                                             float* __restrict__ out,
                                             int n_thread_units)  // total_groups / 4
{
    int t = blockIdx.x * blockDim.x + threadIdx.x;
    if (t >= n_thread_units) return;

    const int g0  = t << 2;                 // first group index (flat)
    const int k   = g0 & (GROUPS_PER_ROW - 1);
    const int row = g0 >> 13;               // g0 / 8192

    const float* __restrict__ xin = x + (size_t)g0 * 8;

    const float S = 0.35355339059327373f;   // (1/sqrt2)^3

    float r0[4], r1[4], r2[4], r3[4], r4[4], r5[4], r6[4], r7[4];

#pragma unroll
    for (int q = 0; q < 4; q++) {
        float v0, v1, v2, v3, v4, v5, v6, v7;
        // 256-bit read-only global load (sm_100+): one LDG.E.256 per group.
        asm("ld.global.nc.v8.f32 {%0,%1,%2,%3,%4,%5,%6,%7}, [%8];"
            : "=f"(v0), "=f"(v1), "=f"(v2), "=f"(v3),
              "=f"(v4), "=f"(v5), "=f"(v6), "=f"(v7)
            : "l"(xin + q * 8));

        // level 1: pairwise sum/diff
        float p0 = v0 + v1, m0 = v0 - v1;
        float p1 = v2 + v3, m1 = v2 - v3;
        float p2 = v4 + v5, m2 = v4 - v5;
        float p3 = v6 + v7, m3 = v6 - v7;

        // level 2
        float pp0 = p0 + p1, pm0 = p0 - p1;
        float pp1 = p2 + p3, pm1 = p2 - p3;
        float mp0 = m0 + m1, mm0 = m0 - m1;
        float mp1 = m2 + m3, mm1 = m2 - m3;

        // level 3 + Gray-code output permutation [0,1,3,2,6,7,5,4]
        r0[q] = (pp0 + pp1) * S;   // nat0 aaa
        r1[q] = (pp0 - pp1) * S;   // nat1 aad
        r2[q] = (pm0 - pm1) * S;   // nat3 add
        r3[q] = (pm0 + pm1) * S;   // nat2 ada
        r4[q] = (mm0 + mm1) * S;   // nat6 dda
        r5[q] = (mm0 - mm1) * S;   // nat7 ddd
        r6[q] = (mp0 - mp1) * S;   // nat5 dad
        r7[q] = (mp0 + mp1) * S;   // nat4 daa
    }

    float* __restrict__ ob = out + (size_t)row * ROW_LEN + k;
#define WR(i, a) __stcs(reinterpret_cast<float4*>(ob + (i) * GROUPS_PER_ROW), \
                        make_float4(a[0], a[1], a[2], a[3]))
    WR(0, r0); WR(1, r1); WR(2, r2); WR(3, r3);
    WR(4, r4); WR(5, r5); WR(6, r6); WR(7, r7);
#undef WR
}

extern "C" void kernel_launch(void* const* d_in, const int* in_sizes, int n_in,
                              void* d_out, int out_size)
{
    const float* x = (const float*)d_in[0];
    float* out = (float*)d_out;

    // total elements = 67,108,864; groups = /8; thread units = groups/4
    int n_thread_units = in_sizes[0] / 32;
    int block = 512;
    int grid = (n_thread_units + block - 1) / block;   // 4096 one-shot blocks
    WaveletPacketTransform_74715251081585_kernel<<<grid, block>>>(x, out, n_thread_units);
}